// round 14
// baseline (speedup 1.0000x reference)
#include <cuda_runtime.h>

#define BB 64      // batch
#define SS 512     // sequence length
#define EE 256     // embedding dim
#define HH 512     // hidden
#define GG 2048    // 4*H gate rows

typedef unsigned long long u64;
typedef unsigned int u32;
typedef unsigned short u16;

// ---------------------------------------------------------------------------
// Device globals
// ---------------------------------------------------------------------------
__device__ u32 g_wf[128];                     // per-CTA h write-flags (monotonic)
__device__ float g_xg[SS * GG * BB];          // x_gates [s][g][b]
__device__ u16 g_hhi[4][BB * HH];             // h ring, bf16 hi part, [b][k]
__device__ u16 g_hlo[4][BB * HH];             // h ring, bf16 lo part, [b][k]

// ---------------------------------------------------------------------------
// f32x2 helpers (packed FFMA2 -- only reachable via PTX) -- used in phase A
// ---------------------------------------------------------------------------
__device__ __forceinline__ u64 fma2(u64 a, u64 b, u64 c) {
    u64 d; asm("fma.rn.f32x2 %0, %1, %2, %3;" : "=l"(d) : "l"(a), "l"(b), "l"(c)); return d;
}
__device__ __forceinline__ float2 unpack2(u64 v) {
    float2 r; asm("mov.b64 {%0, %1}, %2;" : "=f"(r.x), "=f"(r.y) : "l"(v)); return r;
}
__device__ __forceinline__ float sigf(float x) { return 1.f / (1.f + __expf(-x)); }
__device__ __forceinline__ float tanh_f(float x) { return 2.f / (1.f + __expf(-2.f * x)) - 1.f; }

// bf16 helpers
__device__ __forceinline__ u16 f2bf(float x) {
    u16 r; asm("cvt.rn.bf16.f32 %0, %1;" : "=h"(r) : "f"(x)); return r;
}
__device__ __forceinline__ float bf2f(u16 b) {
    return __uint_as_float((u32)b << 16);
}

// mma.sync m16n8k16 bf16: D(f32) += A(bf16) * B(bf16)
__device__ __forceinline__ void mma_bf16(float* d, const u32* a, const u32* b) {
    asm volatile(
        "mma.sync.aligned.m16n8k16.row.col.f32.bf16.bf16.f32 "
        "{%0,%1,%2,%3}, {%4,%5,%6,%7}, {%8,%9}, {%0,%1,%2,%3};"
        : "+f"(d[0]), "+f"(d[1]), "+f"(d[2]), "+f"(d[3])
        : "r"(a[0]), "r"(a[1]), "r"(a[2]), "r"(a[3]), "r"(b[0]), "r"(b[1]));
}

// ---------------------------------------------------------------------------
// Phase A: x_gates[s][g][b] = emb[seq[b][s]] . W_ih[g] + b_ih[g] + b_hh[g]
// (R10 version, measured ~928us, unchanged)
// ---------------------------------------------------------------------------
__global__ void __launch_bounds__(256) xgates_gemm(
    const void* __restrict__ seq,
    const float* __restrict__ emb,
    const float* __restrict__ Wih,
    const float* __restrict__ bih,
    const float* __restrict__ bhh)
{
    __shared__ float  As[16][132];
    __shared__ float2 Bs2[16][66];
    __shared__ int rows[128];
    __shared__ int s_is64;

    const int tid = threadIdx.x;
    const int s0 = blockIdx.y * 2;
    const int g0 = blockIdx.x * 64;

    if (tid == 0) s_is64 = 1;
    __syncthreads();
    if (tid < 64) {
        if (((const u32*)seq)[2 * tid + 1] != 0u) s_is64 = 0;
    }
    __syncthreads();
    if (tid < 128) {
        int b = tid & 63, sl = tid >> 6;
        int idx;
        if (s_is64) idx = (int)((const long long*)seq)[b * SS + s0 + sl];
        else        idx = ((const int*)seq)[b * SS + s0 + sl];
        rows[tid] = idx;
    }
    __syncthreads();

    const int tx = tid & 15;
    const int ty = tid >> 4;
    const int arow = tid >> 1;
    const int ak   = (tid & 1) * 8;
    const int wrow = tid >> 2;
    const int wk   = (tid & 3) * 4;

    const float* aptr = emb + (size_t)rows[arow] * EE + ak;
    const float* wptr = Wih + (size_t)(g0 + wrow) * EE + wk;

    u64 cc[4][4];
    #pragma unroll
    for (int p = 0; p < 4; p++)
        #pragma unroll
        for (int jn = 0; jn < 4; jn++) cc[p][jn] = 0ull;

    float4 ra0 = *(const float4*)aptr;
    float4 ra1 = *(const float4*)(aptr + 4);
    float4 rw  = *(const float4*)wptr;

    for (int k0 = 0; k0 < EE; k0 += 16) {
        As[ak + 0][arow] = ra0.x; As[ak + 1][arow] = ra0.y;
        As[ak + 2][arow] = ra0.z; As[ak + 3][arow] = ra0.w;
        As[ak + 4][arow] = ra1.x; As[ak + 5][arow] = ra1.y;
        As[ak + 6][arow] = ra1.z; As[ak + 7][arow] = ra1.w;
        Bs2[wk + 0][wrow] = make_float2(rw.x, rw.x);
        Bs2[wk + 1][wrow] = make_float2(rw.y, rw.y);
        Bs2[wk + 2][wrow] = make_float2(rw.z, rw.z);
        Bs2[wk + 3][wrow] = make_float2(rw.w, rw.w);
        __syncthreads();

        if (k0 + 16 < EE) {
            ra0 = *(const float4*)(aptr + k0 + 16);
            ra1 = *(const float4*)(aptr + k0 + 20);
            rw  = *(const float4*)(wptr + k0 + 16);
        }

        #pragma unroll
        for (int kk = 0; kk < 16; kk++) {
            u64 a0p = *(const u64*)&As[kk][0 * 32 + tx * 2];
            u64 a1p = *(const u64*)&As[kk][1 * 32 + tx * 2];
            u64 a2p = *(const u64*)&As[kk][2 * 32 + tx * 2];
            u64 a3p = *(const u64*)&As[kk][3 * 32 + tx * 2];
            u64 w0 = *(const u64*)&Bs2[kk][ty * 4 + 0];
            u64 w1 = *(const u64*)&Bs2[kk][ty * 4 + 1];
            u64 w2 = *(const u64*)&Bs2[kk][ty * 4 + 2];
            u64 w3 = *(const u64*)&Bs2[kk][ty * 4 + 3];
            cc[0][0] = fma2(a0p, w0, cc[0][0]); cc[1][0] = fma2(a1p, w0, cc[1][0]);
            cc[2][0] = fma2(a2p, w0, cc[2][0]); cc[3][0] = fma2(a3p, w0, cc[3][0]);
            cc[0][1] = fma2(a0p, w1, cc[0][1]); cc[1][1] = fma2(a1p, w1, cc[1][1]);
            cc[2][1] = fma2(a2p, w1, cc[2][1]); cc[3][1] = fma2(a3p, w1, cc[3][1]);
            cc[0][2] = fma2(a0p, w2, cc[0][2]); cc[1][2] = fma2(a1p, w2, cc[1][2]);
            cc[2][2] = fma2(a2p, w2, cc[2][2]); cc[3][2] = fma2(a3p, w2, cc[3][2]);
            cc[0][3] = fma2(a0p, w3, cc[0][3]); cc[1][3] = fma2(a1p, w3, cc[1][3]);
            cc[2][3] = fma2(a2p, w3, cc[2][3]); cc[3][3] = fma2(a3p, w3, cc[3][3]);
        }
        __syncthreads();
    }

    #pragma unroll
    for (int jn = 0; jn < 4; jn++) {
        int g = g0 + ty * 4 + jn;
        float bsum = bih[g] + bhh[g];
        #pragma unroll
        for (int p = 0; p < 4; p++) {
            float2 v = unpack2(cc[p][jn]);
            int s = s0 + (p >> 1);
            int b = (p & 1) * 32 + tx * 2;
            *(float2*)&g_xg[(size_t)s * (GG * BB) + (size_t)g * BB + b] =
                make_float2(v.x + bsum, v.y + bsum);
        }
    }
}

// ---------------------------------------------------------------------------
// Phase B: persistent LSTM recurrence on TENSOR CORES (mma.sync bf16 hi/lo).
// 128 CTAs x 256 threads (8 warps). CTA owns 4 h-columns j0..j0+3 ->
// 16 gate rows r = g*4 + jl (M dim of the mma). Warp wi owns k-range
// [wi*64,+64) = 4 k-tiles of 16. W_hh split bf16 hi/lo ONCE into stationary
// A-fragments (32 regs). h arrives as two bf16 rings [b][k] written by the
// epilogue; B-fragments are single u32 loads. 3 mma products per tile
// (hi*hi + hi*lo + lo*hi), fp32 accumulators. Sync = R10's proven skeleton.
// SMEM: reduce scratch 32KB only.
// ---------------------------------------------------------------------------
__global__ void __launch_bounds__(256, 1) lstm_kernel(
    const float* __restrict__ Whh, float* __restrict__ out, int write_c)
{
    extern __shared__ float smf[];
    float* scr = smf;                       // [w8][r16][b64] f32 = 32KB
    __shared__ u32 s_base;

    const int tid  = threadIdx.x;
    const int wi   = tid >> 5;
    const int lane = tid & 31;
    const int gid  = lane >> 2;             // 0..7
    const int tig  = lane & 3;              // 0..3
    const int cta  = blockIdx.x;
    const int j0   = cta * 4;
    const int kbase = wi * 64;

    if (tid == 0) s_base = g_wf[cta];

    // ---- stationary A-fragments: W_hh rows r=g*4+jl, split bf16 hi/lo ----
    // a0:(r=gid,  k=tig*2..+1)  a1:(r=gid+8, same k)
    // a2:(r=gid,  k+8)          a3:(r=gid+8, k+8)
    u32 Ahi[4][4], Alo[4][4];
    #pragma unroll
    for (int kt = 0; kt < 4; kt++) {
        #pragma unroll
        for (int q = 0; q < 4; q++) {
            int r  = (q & 1) ? gid + 8 : gid;
            int kc = kbase + kt * 16 + tig * 2 + ((q >> 1) ? 8 : 0);
            int grow = (r >> 2) * HH + j0 + (r & 3);
            float w0 = Whh[(size_t)grow * HH + kc];
            float w1 = Whh[(size_t)grow * HH + kc + 1];
            u16 h0 = f2bf(w0), h1 = f2bf(w1);
            float l0 = w0 - bf2f(h0), l1 = w1 - bf2f(h1);
            Ahi[kt][q] = (u32)h0 | ((u32)h1 << 16);
            Alo[kt][q] = (u32)f2bf(l0) | ((u32)f2bf(l1) << 16);
        }
    }
    __syncthreads();

    const int b  = tid & 63;        // epilogue: one (b, j) per thread
    const int jj = tid >> 6;        // 0..3
    const int j  = j0 + jj;
    const u32 base = s_base;

    float c_reg = 0.f, h_val = 0.f;

    #pragma unroll 1
    for (int s = 0; s < SS; s++) {
        // xg precomputed: L2-resident from GEMM
        float xgv[4];
        {
            const float* xgs = g_xg + (size_t)s * (GG * BB);
            #pragma unroll
            for (int g = 0; g < 4; g++)
                xgv[g] = __ldg(&xgs[(g * HH + j) * BB + b]);
        }

        float C[8][4];
        #pragma unroll
        for (int bt = 0; bt < 8; bt++)
            #pragma unroll
            for (int q = 0; q < 4; q++) C[bt][q] = 0.f;

        if (s > 0) {
            // single wait: the 16 producer CTAs of OUR k-range
            const u32 target = base + (u32)s;
            int ok, first = 1;
            do {
                if (!first) __nanosleep(20);
                first = 0;
                ok = 1;
                if (lane < 16) {
                    u32 f;
                    asm volatile("ld.acquire.gpu.global.u32 %0, [%1];"
                                 : "=r"(f) : "l"(&g_wf[wi * 16 + lane]));
                    ok = ((int)(f - target) >= 0);
                }
            } while (__all_sync(0xffffffffu, ok) == 0);

            const u32* rh = (const u32*)g_hhi[(s - 1) & 3];   // [b][k] bf16
            const u32* rl = (const u32*)g_hlo[(s - 1) & 3];

            // B-frags: b0:(k=tig*2..+1, n=bt*8+gid)  b1:(k+8..+9, same n)
            u32 Bh[2][16], Bl[2][16];
            #pragma unroll
            for (int bt = 0; bt < 8; bt++) {    // prefetch k-tile 0
                int idx = ((bt * 8 + gid) * HH + kbase + tig * 2) >> 1;
                Bh[0][bt * 2 + 0] = __ldcg(&rh[idx]);
                Bh[0][bt * 2 + 1] = __ldcg(&rh[idx + 4]);
                Bl[0][bt * 2 + 0] = __ldcg(&rl[idx]);
                Bl[0][bt * 2 + 1] = __ldcg(&rl[idx + 4]);
            }

            #pragma unroll
            for (int kt = 0; kt < 4; kt++) {
                const int cur = kt & 1;
                if (kt < 3) {
                    const int nxt = cur ^ 1;
                    #pragma unroll
                    for (int bt = 0; bt < 8; bt++) {
                        int idx = ((bt * 8 + gid) * HH + kbase + (kt + 1) * 16
                                   + tig * 2) >> 1;
                        Bh[nxt][bt * 2 + 0] = __ldcg(&rh[idx]);
                        Bh[nxt][bt * 2 + 1] = __ldcg(&rh[idx + 4]);
                        Bl[nxt][bt * 2 + 0] = __ldcg(&rl[idx]);
                        Bl[nxt][bt * 2 + 1] = __ldcg(&rl[idx + 4]);
                    }
                }
                #pragma unroll
                for (int bt = 0; bt < 8; bt++) {
                    mma_bf16(C[bt], Ahi[kt], &Bh[cur][bt * 2]);   // hi*hi
                    mma_bf16(C[bt], Ahi[kt], &Bl[cur][bt * 2]);   // hi*lo
                    mma_bf16(C[bt], Alo[kt], &Bh[cur][bt * 2]);   // lo*hi
                }
            }
        }

        // ---- partials -> scratch [w][r][b] ----
        // c0,c1:(r=gid,  b=bt*8+tig*2, +1)   c2,c3:(r=gid+8, same b)
        #pragma unroll
        for (int bt = 0; bt < 8; bt++) {
            int bcol = bt * 8 + tig * 2;
            *(float2*)&scr[(wi * 16 + gid) * 64 + bcol] =
                make_float2(C[bt][0], C[bt][1]);
            *(float2*)&scr[(wi * 16 + gid + 8) * 64 + bcol] =
                make_float2(C[bt][2], C[bt][3]);
        }
        __syncthreads();

        // ---- cross-warp reduce (8 k-range partials) + gates ----
        float gt[4];
        #pragma unroll
        for (int g = 0; g < 4; g++) {
            int r = g * 4 + jj;
            float sum = xgv[g];
            #pragma unroll
            for (int w = 0; w < 8; w++)
                sum += scr[(w * 16 + r) * 64 + b];
            gt[g] = sum;
        }
        float ig = sigf(gt[0]), fg = sigf(gt[1]);
        float gg = tanh_f(gt[2]), og = sigf(gt[3]);
        c_reg = fg * c_reg + ig * gg;
        h_val = og * tanh_f(c_reg);

        // ---- h -> bf16 hi/lo rings [b][k] ----
        {
            u16 hi = f2bf(h_val);
            u16 lo = f2bf(h_val - bf2f(hi));
            g_hhi[s & 3][b * HH + j] = hi;
            g_hlo[s & 3][b * HH + j] = lo;
        }
        __syncthreads();   // all ring stores of this CTA issued before bump
        if (tid == 0) {
            asm volatile("red.release.gpu.global.add.u32 [%0], %1;"
                         :: "l"(&g_wf[cta]), "r"(1u) : "memory");
        }
    }

    out[b * HH + j] = h_val;
    if (write_c) out[BB * HH + b * HH + j] = c_reg;
}

// ---------------------------------------------------------------------------
// kernel_launch
// ---------------------------------------------------------------------------
extern "C" void kernel_launch(void* const* d_in, const int* in_sizes, int n_in,
                              void* d_out, int out_size)
{
    const void*  seq = d_in[0];
    const float* emb = (const float*)d_in[1];
    const float* Wih = (const float*)d_in[2];
    const float* Whh = (const float*)d_in[3];
    const float* bih = (const float*)d_in[4];
    const float* bhh = (const float*)d_in[5];
    float* out = (float*)d_out;

    (void)in_sizes; (void)n_in;
    int write_c = (out_size >= 2 * BB * HH) ? 1 : 0;

    // 32 KB dynamic SMEM: reduce scratch only (W lives in registers)
    static const int kSmem = 8192 * (int)sizeof(float);
    cudaFuncSetAttribute(lstm_kernel, cudaFuncAttributeMaxDynamicSharedMemorySize, kSmem);

    xgates_gemm<<<dim3(GG / 64, SS / 2), 256>>>(seq, emb, Wih, bih, bhh);
    lstm_kernel<<<HH / 4, 256, kSmem>>>(Whh, out, write_c);
}

// round 15
// speedup vs baseline: 1.3605x; 1.3605x over previous
#include <cuda_runtime.h>

#define BB 64      // batch
#define SS 512     // sequence length
#define EE 256     // embedding dim
#define HH 512     // hidden
#define GG 2048    // 4*H gate rows

typedef unsigned long long u64;
typedef unsigned int u32;
typedef unsigned short u16;

// ---------------------------------------------------------------------------
// Device globals
// ---------------------------------------------------------------------------
__device__ u32 g_wf[128];                     // per-CTA h write-flags (monotonic)
__device__ float g_xg[SS * GG * BB];          // x_gates [s][g][b]
__device__ u16 g_hhi[4][BB * HH];             // h ring, bf16 hi part, [b][k]
__device__ u16 g_hlo[4][BB * HH];             // h ring, bf16 lo part, [b][k]

// ---------------------------------------------------------------------------
// f32x2 helpers (phase A) + misc
// ---------------------------------------------------------------------------
__device__ __forceinline__ u64 fma2(u64 a, u64 b, u64 c) {
    u64 d; asm("fma.rn.f32x2 %0, %1, %2, %3;" : "=l"(d) : "l"(a), "l"(b), "l"(c)); return d;
}
__device__ __forceinline__ float2 unpack2(u64 v) {
    float2 r; asm("mov.b64 {%0, %1}, %2;" : "=f"(r.x), "=f"(r.y) : "l"(v)); return r;
}
__device__ __forceinline__ float sigf(float x) { return 1.f / (1.f + __expf(-x)); }
__device__ __forceinline__ float tanh_f(float x) { return 2.f / (1.f + __expf(-2.f * x)) - 1.f; }

__device__ __forceinline__ u16 f2bf(float x) {
    u16 r; asm("cvt.rn.bf16.f32 %0, %1;" : "=h"(r) : "f"(x)); return r;
}
__device__ __forceinline__ float bf2f(u16 b) {
    return __uint_as_float((u32)b << 16);
}

// mma.sync m16n8k16 bf16: D(f32) += A(bf16) * B(bf16)
__device__ __forceinline__ void mma_bf16(float* d, const u32* a, u32 b0, u32 b1) {
    asm volatile(
        "mma.sync.aligned.m16n8k16.row.col.f32.bf16.bf16.f32 "
        "{%0,%1,%2,%3}, {%4,%5,%6,%7}, {%8,%9}, {%0,%1,%2,%3};"
        : "+f"(d[0]), "+f"(d[1]), "+f"(d[2]), "+f"(d[3])
        : "r"(a[0]), "r"(a[1]), "r"(a[2]), "r"(a[3]), "r"(b0), "r"(b1));
}

// ---------------------------------------------------------------------------
// Phase A: x_gates GEMM (R10 version, measured ~928us, unchanged)
// ---------------------------------------------------------------------------
__global__ void __launch_bounds__(256) xgates_gemm(
    const void* __restrict__ seq,
    const float* __restrict__ emb,
    const float* __restrict__ Wih,
    const float* __restrict__ bih,
    const float* __restrict__ bhh)
{
    __shared__ float  As[16][132];
    __shared__ float2 Bs2[16][66];
    __shared__ int rows[128];
    __shared__ int s_is64;

    const int tid = threadIdx.x;
    const int s0 = blockIdx.y * 2;
    const int g0 = blockIdx.x * 64;

    if (tid == 0) s_is64 = 1;
    __syncthreads();
    if (tid < 64) {
        if (((const u32*)seq)[2 * tid + 1] != 0u) s_is64 = 0;
    }
    __syncthreads();
    if (tid < 128) {
        int b = tid & 63, sl = tid >> 6;
        int idx;
        if (s_is64) idx = (int)((const long long*)seq)[b * SS + s0 + sl];
        else        idx = ((const int*)seq)[b * SS + s0 + sl];
        rows[tid] = idx;
    }
    __syncthreads();

    const int tx = tid & 15;
    const int ty = tid >> 4;
    const int arow = tid >> 1;
    const int ak   = (tid & 1) * 8;
    const int wrow = tid >> 2;
    const int wk   = (tid & 3) * 4;

    const float* aptr = emb + (size_t)rows[arow] * EE + ak;
    const float* wptr = Wih + (size_t)(g0 + wrow) * EE + wk;

    u64 cc[4][4];
    #pragma unroll
    for (int p = 0; p < 4; p++)
        #pragma unroll
        for (int jn = 0; jn < 4; jn++) cc[p][jn] = 0ull;

    float4 ra0 = *(const float4*)aptr;
    float4 ra1 = *(const float4*)(aptr + 4);
    float4 rw  = *(const float4*)wptr;

    for (int k0 = 0; k0 < EE; k0 += 16) {
        As[ak + 0][arow] = ra0.x; As[ak + 1][arow] = ra0.y;
        As[ak + 2][arow] = ra0.z; As[ak + 3][arow] = ra0.w;
        As[ak + 4][arow] = ra1.x; As[ak + 5][arow] = ra1.y;
        As[ak + 6][arow] = ra1.z; As[ak + 7][arow] = ra1.w;
        Bs2[wk + 0][wrow] = make_float2(rw.x, rw.x);
        Bs2[wk + 1][wrow] = make_float2(rw.y, rw.y);
        Bs2[wk + 2][wrow] = make_float2(rw.z, rw.z);
        Bs2[wk + 3][wrow] = make_float2(rw.w, rw.w);
        __syncthreads();

        if (k0 + 16 < EE) {
            ra0 = *(const float4*)(aptr + k0 + 16);
            ra1 = *(const float4*)(aptr + k0 + 20);
            rw  = *(const float4*)(wptr + k0 + 16);
        }

        #pragma unroll
        for (int kk = 0; kk < 16; kk++) {
            u64 a0p = *(const u64*)&As[kk][0 * 32 + tx * 2];
            u64 a1p = *(const u64*)&As[kk][1 * 32 + tx * 2];
            u64 a2p = *(const u64*)&As[kk][2 * 32 + tx * 2];
            u64 a3p = *(const u64*)&As[kk][3 * 32 + tx * 2];
            u64 w0 = *(const u64*)&Bs2[kk][ty * 4 + 0];
            u64 w1 = *(const u64*)&Bs2[kk][ty * 4 + 1];
            u64 w2 = *(const u64*)&Bs2[kk][ty * 4 + 2];
            u64 w3 = *(const u64*)&Bs2[kk][ty * 4 + 3];
            cc[0][0] = fma2(a0p, w0, cc[0][0]); cc[1][0] = fma2(a1p, w0, cc[1][0]);
            cc[2][0] = fma2(a2p, w0, cc[2][0]); cc[3][0] = fma2(a3p, w0, cc[3][0]);
            cc[0][1] = fma2(a0p, w1, cc[0][1]); cc[1][1] = fma2(a1p, w1, cc[1][1]);
            cc[2][1] = fma2(a2p, w1, cc[2][1]); cc[3][1] = fma2(a3p, w1, cc[3][1]);
            cc[0][2] = fma2(a0p, w2, cc[0][2]); cc[1][2] = fma2(a1p, w2, cc[1][2]);
            cc[2][2] = fma2(a2p, w2, cc[2][2]); cc[3][2] = fma2(a3p, w2, cc[3][2]);
            cc[0][3] = fma2(a0p, w3, cc[0][3]); cc[1][3] = fma2(a1p, w3, cc[1][3]);
            cc[2][3] = fma2(a2p, w3, cc[2][3]); cc[3][3] = fma2(a3p, w3, cc[3][3]);
        }
        __syncthreads();
    }

    #pragma unroll
    for (int jn = 0; jn < 4; jn++) {
        int g = g0 + ty * 4 + jn;
        float bsum = bih[g] + bhh[g];
        #pragma unroll
        for (int p = 0; p < 4; p++) {
            float2 v = unpack2(cc[p][jn]);
            int s = s0 + (p >> 1);
            int b = (p & 1) * 32 + tx * 2;
            *(float2*)&g_xg[(size_t)s * (GG * BB) + (size_t)g * BB + b] =
                make_float2(v.x + bsum, v.y + bsum);
        }
    }
}

// ---------------------------------------------------------------------------
// Phase B: tensor-core LSTM recurrence with coalesced SMEM staging.
// 128 CTAs x 256 threads (8 warps). CTA owns 4 h-columns -> 16 gate rows
// (M dim). Warp wi owns k-range [wi*64,+64). W_hh hi/lo stationary in
// A-fragments. Per step: warp stages its [64 b x 64 k] hi/lo tiles from the
// bf16 rings via LDG.128->STS.128 (full 128B lines), then B-fragments via
// conflict-free LDS.32 (row stride 260 u32 -> bank = 4*gid+tig). Staging is
// warp-private (reads only own k columns) -> __syncwarp only.
// SMEM: hs_hi 65KB | hs_lo 65KB | scratch 32KB = 162KB.
// ---------------------------------------------------------------------------
#define HSTRIDE 260   // u32 per b-row in staged tiles

__global__ void __launch_bounds__(256, 1) lstm_kernel(
    const float* __restrict__ Whh, float* __restrict__ out, int write_c)
{
    extern __shared__ u32 smu[];
    u32*   hsh = smu;                        // [64][HSTRIDE] u32 (bf16 pairs)
    u32*   hsl = smu + 64 * HSTRIDE;
    float* scr = (float*)(smu + 2 * 64 * HSTRIDE);  // [w8][r16][b64] f32
    __shared__ u32 s_base;

    const int tid  = threadIdx.x;
    const int wi   = tid >> 5;
    const int lane = tid & 31;
    const int gid  = lane >> 2;             // 0..7
    const int tig  = lane & 3;              // 0..3
    const int cta  = blockIdx.x;
    const int j0   = cta * 4;
    const int kbase = wi * 64;

    if (tid == 0) s_base = g_wf[cta];

    // ---- stationary A-fragments: W_hh rows r=g*4+jl, split bf16 hi/lo ----
    u32 Ahi[4][4], Alo[4][4];
    #pragma unroll
    for (int kt = 0; kt < 4; kt++) {
        #pragma unroll
        for (int q = 0; q < 4; q++) {
            int r  = (q & 1) ? gid + 8 : gid;
            int kc = kbase + kt * 16 + tig * 2 + ((q >> 1) ? 8 : 0);
            int grow = (r >> 2) * HH + j0 + (r & 3);
            float w0 = Whh[(size_t)grow * HH + kc];
            float w1 = Whh[(size_t)grow * HH + kc + 1];
            u16 h0 = f2bf(w0), h1 = f2bf(w1);
            float l0 = w0 - bf2f(h0), l1 = w1 - bf2f(h1);
            Ahi[kt][q] = (u32)h0 | ((u32)h1 << 16);
            Alo[kt][q] = (u32)f2bf(l0) | ((u32)f2bf(l1) << 16);
        }
    }
    __syncthreads();

    const int b  = tid & 63;        // epilogue: one (b, j) per thread
    const int jj = tid >> 6;        // 0..3
    const int j  = j0 + jj;
    const u32 base = s_base;

    float c_reg = 0.f, h_val = 0.f;

    #pragma unroll 1
    for (int s = 0; s < SS; s++) {
        // xg precomputed: L2-resident from GEMM
        float xgv[4];
        {
            const float* xgs = g_xg + (size_t)s * (GG * BB);
            #pragma unroll
            for (int g = 0; g < 4; g++)
                xgv[g] = __ldg(&xgs[(g * HH + j) * BB + b]);
        }

        float C[8][4];
        #pragma unroll
        for (int bt = 0; bt < 8; bt++)
            #pragma unroll
            for (int q = 0; q < 4; q++) C[bt][q] = 0.f;

        if (s > 0) {
            // single wait: the 16 producer CTAs of OUR k-range
            const u32 target = base + (u32)s;
            int ok, first = 1;
            do {
                if (!first) __nanosleep(20);
                first = 0;
                ok = 1;
                if (lane < 16) {
                    u32 f;
                    asm volatile("ld.acquire.gpu.global.u32 %0, [%1];"
                                 : "=r"(f) : "l"(&g_wf[wi * 16 + lane]));
                    ok = ((int)(f - target) >= 0);
                }
            } while (__all_sync(0xffffffffu, ok) == 0);

            // ---- stage warp tile [64 b][64 k] hi+lo, coalesced 16B ----
            // flat = it*32 + lane = brow*8 + c16 ; global uint4 idx = brow*64 + wi*8 + c16
            const uint4* ghi = (const uint4*)g_hhi[(s - 1) & 3];
            const uint4* glo = (const uint4*)g_hlo[(s - 1) & 3];
            #pragma unroll
            for (int it = 0; it < 8; it++) {
                int flat = it * 32 + lane;
                int brow = flat >> 3, c16 = flat & 7;
                uint4 v = __ldcg(&ghi[brow * 64 + wi * 8 + c16]);
                *(uint4*)&hsh[brow * HSTRIDE + wi * 32 + c16 * 4] = v;
            }
            #pragma unroll
            for (int it = 8; it < 16; it++) {
                int flat = (it - 8) * 32 + lane + 256;   // brows 32..63
                int brow = flat >> 3, c16 = flat & 7;
                uint4 v = __ldcg(&ghi[brow * 64 + wi * 8 + c16]);
                *(uint4*)&hsh[brow * HSTRIDE + wi * 32 + c16 * 4] = v;
            }
            #pragma unroll
            for (int it = 0; it < 16; it++) {
                int flat = it * 32 + lane;
                int brow = flat >> 3, c16 = flat & 7;
                uint4 v = __ldcg(&glo[brow * 64 + wi * 8 + c16]);
                *(uint4*)&hsl[brow * HSTRIDE + wi * 32 + c16 * 4] = v;
            }
            __syncwarp();

            // ---- mma: B-frags from SMEM (conflict-free LDS.32) ----
            #pragma unroll
            for (int kt = 0; kt < 4; kt++) {
                const int kcol = wi * 32 + kt * 8 + tig;   // u32 col of (k,k+1)
                #pragma unroll
                for (int bt = 0; bt < 8; bt++) {
                    const int rowb = (bt * 8 + gid) * HSTRIDE;
                    u32 bh0 = hsh[rowb + kcol];
                    u32 bh1 = hsh[rowb + kcol + 4];
                    u32 bl0 = hsl[rowb + kcol];
                    u32 bl1 = hsl[rowb + kcol + 4];
                    mma_bf16(C[bt], Ahi[kt], bh0, bh1);   // hi*hi
                    mma_bf16(C[bt], Ahi[kt], bl0, bl1);   // hi*lo
                    mma_bf16(C[bt], Alo[kt], bh0, bh1);   // lo*hi
                }
            }
        }

        // ---- partials -> scratch [w][r][b] ----
        #pragma unroll
        for (int bt = 0; bt < 8; bt++) {
            int bcol = bt * 8 + tig * 2;
            *(float2*)&scr[(wi * 16 + gid) * 64 + bcol] =
                make_float2(C[bt][0], C[bt][1]);
            *(float2*)&scr[(wi * 16 + gid + 8) * 64 + bcol] =
                make_float2(C[bt][2], C[bt][3]);
        }
        __syncthreads();

        // ---- cross-warp reduce (8 k-range partials) + gates ----
        float gt[4];
        #pragma unroll
        for (int g = 0; g < 4; g++) {
            int r = g * 4 + jj;
            float sum = xgv[g];
            #pragma unroll
            for (int w = 0; w < 8; w++)
                sum += scr[(w * 16 + r) * 64 + b];
            gt[g] = sum;
        }
        float ig = sigf(gt[0]), fg = sigf(gt[1]);
        float gg = tanh_f(gt[2]), og = sigf(gt[3]);
        c_reg = fg * c_reg + ig * gg;
        h_val = og * tanh_f(c_reg);

        // ---- h -> bf16 hi/lo rings [b][k] ----
        {
            u16 hi = f2bf(h_val);
            u16 lo = f2bf(h_val - bf2f(hi));
            g_hhi[s & 3][b * HH + j] = hi;
            g_hlo[s & 3][b * HH + j] = lo;
        }
        __syncthreads();   // all ring stores of this CTA issued before bump
        if (tid == 0) {
            asm volatile("red.release.gpu.global.add.u32 [%0], %1;"
                         :: "l"(&g_wf[cta]), "r"(1u) : "memory");
        }
    }

    out[b * HH + j] = h_val;
    if (write_c) out[BB * HH + b * HH + j] = c_reg;
}

// ---------------------------------------------------------------------------
// kernel_launch
// ---------------------------------------------------------------------------
extern "C" void kernel_launch(void* const* d_in, const int* in_sizes, int n_in,
                              void* d_out, int out_size)
{
    const void*  seq = d_in[0];
    const float* emb = (const float*)d_in[1];
    const float* Wih = (const float*)d_in[2];
    const float* Whh = (const float*)d_in[3];
    const float* bih = (const float*)d_in[4];
    const float* bhh = (const float*)d_in[5];
    float* out = (float*)d_out;

    (void)in_sizes; (void)n_in;
    int write_c = (out_size >= 2 * BB * HH) ? 1 : 0;

    // SMEM: 2 x 64 x HSTRIDE u32 (staged h) + 8192 f32 scratch  (~162 KB)
    static const int kSmem = (2 * 64 * HSTRIDE + 8192) * 4;
    cudaFuncSetAttribute(lstm_kernel, cudaFuncAttributeMaxDynamicSharedMemorySize, kSmem);

    xgates_gemm<<<dim3(GG / 64, SS / 2), 256>>>(seq, emb, Wih, bih, bhh);
    lstm_kernel<<<HH / 4, 256, kSmem>>>(Whh, out, write_c);
}

// round 16
// speedup vs baseline: 1.5803x; 1.1616x over previous
#include <cuda_runtime.h>

#define BB 64      // batch
#define SS 512     // sequence length
#define EE 256     // embedding dim
#define HH 512     // hidden
#define GG 2048    // 4*H gate rows

typedef unsigned long long u64;
typedef unsigned int u32;
typedef unsigned short u16;

// ---------------------------------------------------------------------------
// Device globals
// ---------------------------------------------------------------------------
__device__ u32 g_wf[128];                     // per-CTA h write-flags (monotonic)
__device__ float g_xg[SS * GG * BB];          // x_gates [s][g][b]
__device__ float g_h[4][HH * BB];             // h ring: slot s&3 = h(s), [k][b]

// ---------------------------------------------------------------------------
// helpers
// ---------------------------------------------------------------------------
__device__ __forceinline__ u64 fma2(u64 a, u64 b, u64 c) {
    u64 d; asm("fma.rn.f32x2 %0, %1, %2, %3;" : "=l"(d) : "l"(a), "l"(b), "l"(c)); return d;
}
__device__ __forceinline__ u64 add2(u64 a, u64 b) {
    u64 d; asm("add.rn.f32x2 %0, %1, %2;" : "=l"(d) : "l"(a), "l"(b)); return d;
}
__device__ __forceinline__ u64 pack2(float x, float y) {
    u64 d; asm("mov.b64 %0, {%1, %2};" : "=l"(d) : "f"(x), "f"(y)); return d;
}
__device__ __forceinline__ float2 unpack2(u64 v) {
    float2 r; asm("mov.b64 {%0, %1}, %2;" : "=f"(r.x), "=f"(r.y) : "l"(v)); return r;
}
__device__ __forceinline__ float sigf(float x) { return 1.f / (1.f + __expf(-x)); }
__device__ __forceinline__ float tanh_f(float x) { return 2.f / (1.f + __expf(-2.f * x)) - 1.f; }

// packed bf16x2 convert: lo 16 bits = v0, hi 16 bits = v1
__device__ __forceinline__ u32 pack_bf2(float v0, float v1) {
    u32 d; asm("cvt.rn.bf16x2.f32 %0, %1, %2;" : "=r"(d) : "f"(v1), "f"(v0)); return d;
}
// hi/lo split of a float pair into two bf16x2 words
__device__ __forceinline__ void split_bf2(float v0, float v1, u32& hi, u32& lo) {
    hi = pack_bf2(v0, v1);
    float r0 = v0 - __uint_as_float(hi << 16);
    float r1 = v1 - __uint_as_float(hi & 0xffff0000u);
    lo = pack_bf2(r0, r1);
}

// mma.sync m16n8k16 bf16: D(f32) += A(bf16) * B(bf16)
__device__ __forceinline__ void mma_bf16(float* d, const u32* a, u32 b0, u32 b1) {
    asm volatile(
        "mma.sync.aligned.m16n8k16.row.col.f32.bf16.bf16.f32 "
        "{%0,%1,%2,%3}, {%4,%5,%6,%7}, {%8,%9}, {%0,%1,%2,%3};"
        : "+f"(d[0]), "+f"(d[1]), "+f"(d[2]), "+f"(d[3])
        : "r"(a[0]), "r"(a[1]), "r"(a[2]), "r"(a[3]), "r"(b0), "r"(b1));
}

// ---------------------------------------------------------------------------
// Phase A on TENSOR CORES: x_gates[s][g][b] = emb[seq[b][s]].W_ih[g] + bias
// CTA (256 thr, 8 warps): tile M=128 (m = sl*64+b, 2 s x 64 b) x N=64 g x
// K=256. Warp wi owns M-rows [wi*16,+16), all 8 n-tiles, full K (16 k-tiles).
// W_ih staged once in SMEM as bf16 hi/lo, row stride 132 u32 (conflict-free:
// bank = 4*gid + tig). A-frags: direct float2 LDG from emb + in-register
// hi/lo bf16 split. 3 products (hh + hl + lh), fp32 accum (~1e-6 rel).
// Epilogue via padded scratch (stride 65) -> coalesced b-major stores.
// ---------------------------------------------------------------------------
#define WP   132   // u32 stride per W row
#define SCRP 65    // f32 stride per scr row
#define OFF_WSL  (64 * WP)
#define OFF_SCR  (2 * 64 * WP)
#define OFF_BIA  (OFF_SCR + 128 * SCRP)
#define OFF_ROWS (OFF_BIA + 64)
#define OFF_IS64 (OFF_ROWS + 128)
#define GEMM_SMEM_U32 (OFF_IS64 + 1)

__global__ void __launch_bounds__(256) xgates_gemm(
    const void* __restrict__ seq,
    const float* __restrict__ emb,
    const float* __restrict__ Wih,
    const float* __restrict__ bih,
    const float* __restrict__ bhh)
{
    extern __shared__ u32 smu[];
    u32*   wsh   = smu;                       // W hi  [64][WP]
    u32*   wsl   = smu + OFF_WSL;             // W lo  [64][WP]
    float* scr   = (float*)(smu + OFF_SCR);   // [128][SCRP]
    float* sbias = (float*)(smu + OFF_BIA);   // [64]
    int*   rows  = (int*)(smu + OFF_ROWS);    // [128]
    u32*   is64p = smu + OFF_IS64;

    const int tid  = threadIdx.x;
    const int wi   = tid >> 5;
    const int lane = tid & 31;
    const int gid  = lane >> 2;
    const int tig  = lane & 3;
    const int s0 = blockIdx.y * 2;
    const int g0 = blockIdx.x * 64;

    if (tid == 0) *is64p = 1;
    __syncthreads();
    if (tid < 64) {
        if (((const u32*)seq)[2 * tid + 1] != 0u) *is64p = 0;
    }
    __syncthreads();
    if (tid < 128) {
        int b = tid & 63, sl = tid >> 6;
        int idx;
        if (*is64p) idx = (int)((const long long*)seq)[b * SS + s0 + sl];
        else        idx = ((const int*)seq)[b * SS + s0 + sl];
        rows[tid] = idx;
    }

    // stage W_ih hi/lo: thread -> row n = tid>>2, k segment (tid&3)*64
    {
        int n = tid >> 2, kseg = (tid & 3) * 64;
        const float* wr = Wih + (size_t)(g0 + n) * EE + kseg;
        #pragma unroll
        for (int i = 0; i < 16; i++) {
            float4 v = *(const float4*)(wr + i * 4);
            u32 h01, l01, h23, l23;
            split_bf2(v.x, v.y, h01, l01);
            split_bf2(v.z, v.w, h23, l23);
            int c = n * WP + ((kseg + i * 4) >> 1);
            wsh[c] = h01; wsh[c + 1] = h23;
            wsl[c] = l01; wsl[c + 1] = l23;
        }
    }
    if (tid < 64) sbias[tid] = bih[g0 + tid] + bhh[g0 + tid];
    __syncthreads();

    // main: A from global (float2 pairs), B from SMEM, 3 mma per tile
    const int m0 = wi * 16 + gid;
    const float* e0 = emb + (size_t)rows[m0] * EE;
    const float* e1 = emb + (size_t)rows[m0 + 8] * EE;

    float C[8][4];
    #pragma unroll
    for (int nt = 0; nt < 8; nt++)
        #pragma unroll
        for (int q = 0; q < 4; q++) C[nt][q] = 0.f;

    #pragma unroll
    for (int kt = 0; kt < 16; kt++) {
        const int k0 = kt * 16 + tig * 2;
        float2 p00 = *(const float2*)(e0 + k0);
        float2 p10 = *(const float2*)(e1 + k0);
        float2 p01 = *(const float2*)(e0 + k0 + 8);
        float2 p11 = *(const float2*)(e1 + k0 + 8);
        u32 Ah[4], Al[4];
        split_bf2(p00.x, p00.y, Ah[0], Al[0]);
        split_bf2(p10.x, p10.y, Ah[1], Al[1]);
        split_bf2(p01.x, p01.y, Ah[2], Al[2]);
        split_bf2(p11.x, p11.y, Ah[3], Al[3]);

        const int kc = kt * 8 + tig;
        #pragma unroll
        for (int nt = 0; nt < 8; nt++) {
            int rb = (nt * 8 + gid) * WP + kc;
            u32 bh0 = wsh[rb], bh1 = wsh[rb + 4];
            u32 bl0 = wsl[rb], bl1 = wsl[rb + 4];
            mma_bf16(C[nt], Ah, bh0, bh1);   // hi*hi
            mma_bf16(C[nt], Ah, bl0, bl1);   // hi*lo
            mma_bf16(C[nt], Al, bh0, bh1);   // lo*hi
        }
    }

    // C frags -> scratch [m][n]
    #pragma unroll
    for (int nt = 0; nt < 8; nt++) {
        int ncol = nt * 8 + tig * 2;
        scr[(wi * 16 + gid) * SCRP + ncol]     = C[nt][0];
        scr[(wi * 16 + gid) * SCRP + ncol + 1] = C[nt][1];
        scr[(wi * 16 + gid + 8) * SCRP + ncol]     = C[nt][2];
        scr[(wi * 16 + gid + 8) * SCRP + ncol + 1] = C[nt][3];
    }
    __syncthreads();

    // epilogue: thread (b = tid&63, q = tid>>6): sl = q&1, g half = q>>1
    {
        const int b = tid & 63, q = tid >> 6;
        const int sl = q & 1, gh = (q >> 1) * 32;
        const float* src = &scr[(sl * 64 + b) * SCRP];
        float* dst = &g_xg[(size_t)(s0 + sl) * (GG * BB) + (size_t)g0 * BB + b];
        #pragma unroll
        for (int gl = 0; gl < 32; gl++) {
            int g = gh + gl;
            dst[(size_t)g * BB] = src[g] + sbias[g];
        }
    }
}

// ---------------------------------------------------------------------------
// Phase B: persistent LSTM recurrence (R10 exactly -- best measured 2403us).
// ---------------------------------------------------------------------------
__global__ void __launch_bounds__(256, 1) lstm_kernel(
    const float* __restrict__ Whh, float* __restrict__ out, int write_c)
{
    extern __shared__ float smf[];
    float*  Ws  = smf;                      // (st*512+k)*2 : {w_jA, w_jB}
    float2* scp = (float2*)(smf + 8192);    // [st8][kr8][b64] float2
    __shared__ u32 s_base;

    const int tid  = threadIdx.x;
    const int wi   = tid >> 5;
    const int lane = tid & 31;
    const int cta  = blockIdx.x;
    const int j0   = cta * 4;
    const int kbase = wi * 64;

    if (tid == 0) s_base = g_wf[cta];

    #pragma unroll
    for (int st = 0; st < 8; st++) {
        int g = st >> 1, jp = st & 1;
        const float* r0 = Whh + (size_t)(g * HH + j0 + 2 * jp) * HH;
        const float* r1 = r0 + HH;
        #pragma unroll
        for (int i = 0; i < 2; i++) {
            int k = tid + i * 256;
            *(float2*)&Ws[(st * 512 + k) * 2] = make_float2(r0[k], r1[k]);
        }
    }
    __syncthreads();

    const int b  = tid & 63;
    const int jj = tid >> 6;
    const int j  = j0 + jj;
    const int jp_r = jj >> 1;
    const int comp = jj & 1;
    const u32 base = s_base;

    float c_reg = 0.f, h_val = 0.f;

    #pragma unroll 1
    for (int s = 0; s < SS; s++) {
        float xgv[4];
        const float* xgs = g_xg + (size_t)s * (GG * BB);
        #pragma unroll
        for (int g = 0; g < 4; g++)
            xgv[g] = __ldg(&xgs[(g * HH + j) * BB + b]);

        u64 acc[8][2];
        #pragma unroll
        for (int st = 0; st < 8; st++) { acc[st][0] = 0ull; acc[st][1] = 0ull; }

        if (s > 0) {
            const u32 target = base + (u32)s;
            int ok, first = 1;
            do {
                if (!first) __nanosleep(20);
                first = 0;
                ok = 1;
                if (lane < 16) {
                    u32 f;
                    asm volatile("ld.acquire.gpu.global.u32 %0, [%1];"
                                 : "=r"(f) : "l"(&g_wf[wi * 16 + lane]));
                    ok = ((int)(f - target) >= 0);
                }
            } while (__all_sync(0xffffffffu, ok) == 0);

            const float2* hsrc = (const float2*)g_h[(s - 1) & 3];  // [k][b/2]
            float2 hreg[4][8];
            #pragma unroll
            for (int c = 0; c < 3; c++)
                #pragma unroll
                for (int i = 0; i < 8; i++)
                    hreg[c][i] = __ldcg(&hsrc[(kbase + c * 8 + i) * 32 + lane]);

            #pragma unroll
            for (int c = 0; c < 8; c++) {
                const int cur = c & 3;
                if (c < 5) {
                    const int pb = (c + 3) & 3;
                    const int kn = kbase + (c + 3) * 8;
                    #pragma unroll
                    for (int i = 0; i < 8; i++)
                        hreg[pb][i] = __ldcg(&hsrc[(kn + i) * 32 + lane]);
                }
                const int kg0 = kbase + c * 8;
                #pragma unroll
                for (int kk = 0; kk < 8; kk += 2) {
                    const int kg = kg0 + kk;
                    float2 v0 = hreg[cur][kk];
                    float2 v1 = hreg[cur][kk + 1];
                    u64 dA0 = pack2(v0.x, v0.x);
                    u64 dB0 = pack2(v0.y, v0.y);
                    u64 dA1 = pack2(v1.x, v1.x);
                    u64 dB1 = pack2(v1.y, v1.y);
                    #pragma unroll
                    for (int st = 0; st < 8; st++) {
                        ulonglong2 wv = *(const ulonglong2*)&Ws[(st * 512 + kg) * 2];
                        acc[st][0] = fma2(dA0, wv.x, acc[st][0]);
                        acc[st][1] = fma2(dB0, wv.x, acc[st][1]);
                        acc[st][0] = fma2(dA1, wv.y, acc[st][0]);
                        acc[st][1] = fma2(dB1, wv.y, acc[st][1]);
                    }
                }
            }
        }

        #pragma unroll
        for (int st = 0; st < 8; st++) {
            float2 p0 = *(float2*)&acc[st][0];
            float2 p1 = *(float2*)&acc[st][1];
            *(float4*)&scp[(st * 8 + wi) * 64 + 2 * lane] =
                make_float4(p0.x, p0.y, p1.x, p1.y);
        }
        __syncthreads();

        float gt[4];
        #pragma unroll
        for (int g = 0; g < 4; g++) {
            int st = g * 2 + jp_r;
            const u64* rb = (const u64*)&scp[(st * 8) * 64 + b];
            u64 v0 = add2(rb[0 * 64], rb[1 * 64]);
            u64 v1 = add2(rb[2 * 64], rb[3 * 64]);
            u64 v2 = add2(rb[4 * 64], rb[5 * 64]);
            u64 v3 = add2(rb[6 * 64], rb[7 * 64]);
            float2 r = unpack2(add2(add2(v0, v1), add2(v2, v3)));
            gt[g] = (comp ? r.y : r.x) + xgv[g];
        }
        float ig = sigf(gt[0]), fg = sigf(gt[1]);
        float gg = tanh_f(gt[2]), og = sigf(gt[3]);
        c_reg = fg * c_reg + ig * gg;
        h_val = og * tanh_f(c_reg);

        __stcg(&g_h[s & 3][j * 64 + b], h_val);
        __syncthreads();
        if (tid == 0) {
            asm volatile("red.release.gpu.global.add.u32 [%0], %1;"
                         :: "l"(&g_wf[cta]), "r"(1u) : "memory");
        }
    }

    out[b * HH + j] = h_val;
    if (write_c) out[BB * HH + b * HH + j] = c_reg;
}

// ---------------------------------------------------------------------------
// kernel_launch
// ---------------------------------------------------------------------------
extern "C" void kernel_launch(void* const* d_in, const int* in_sizes, int n_in,
                              void* d_out, int out_size)
{
    const void*  seq = d_in[0];
    const float* emb = (const float*)d_in[1];
    const float* Wih = (const float*)d_in[2];
    const float* Whh = (const float*)d_in[3];
    const float* bih = (const float*)d_in[4];
    const float* bhh = (const float*)d_in[5];
    float* out = (float*)d_out;

    (void)in_sizes; (void)n_in;
    int write_c = (out_size >= 2 * BB * HH) ? 1 : 0;

    static const int kGemmSmem = GEMM_SMEM_U32 * 4;             // ~101 KB
    static const int kLstmSmem = (8192 + 8192) * (int)sizeof(float);
    cudaFuncSetAttribute(xgates_gemm, cudaFuncAttributeMaxDynamicSharedMemorySize, kGemmSmem);
    cudaFuncSetAttribute(lstm_kernel, cudaFuncAttributeMaxDynamicSharedMemorySize, kLstmSmem);

    xgates_gemm<<<dim3(GG / 64, SS / 2), 256, kGemmSmem>>>(seq, emb, Wih, bih, bhh);
    lstm_kernel<<<HH / 4, 256, kLstmSmem>>>(Whh, out, write_c);
}